// round 7
// baseline (speedup 1.0000x reference)
#include <cuda_runtime.h>
#include <cuda_bf16.h>

// LSTMHead fused producer/consumer, round 7.
//   Producers: 4096 blocks x 256 thr (R4's proven high-occupancy shape):
//     one row per warp, 8 front-batched LDG.128 per thread, W streamed from
//     smem. launch_bounds(256,4) -> 4 blocks/SM, 32 warps, DRAM latency
//     hidden. Each block bumps its 256-row segment counter when done.
//   Consumers: 128 single-warp blocks at the grid tail; warp w waits for
//     segment counters {w-1, w} == 32, then runs the chunk-parallel scan
//     (4096 chunks of 8 steps, 48 burn-in, one chunk per lane).
//   sigmoid(z) = 0.5 + 0.5*tanh(z/2): sigmoid gates stored as 0.5*g.

#define SEQ   32768
#define DIM   1024
#define CHUNK 8
#define BURN  48
#define NCHUNK (SEQ / CHUNK)        // 4096
#define CWARPS (NCHUNK / 32)        // 128 consumer warps
#define PTHREADS 256
#define ROWS_PER_BLOCK 8            // 8 warps, 1 row each
#define PBLOCKS (SEQ / ROWS_PER_BLOCK)              // 4096
#define SEG_ROWS 256
#define BLOCKS_PER_SEG (SEG_ROWS / ROWS_PER_BLOCK)  // 32
#define NSEG (SEQ / SEG_ROWS)                       // 128
#define TROWS (SEQ / CHUNK)                         // 4096

// transposed, pre-scaled gate pre-activations (512 KB, L2-resident)
__device__ float4 g_gatesT[SEQ];
__device__ int    g_seg[NSEG];

__device__ __forceinline__ int gidx(int t) {
    return (t & (CHUNK - 1)) * TROWS + (t >> 3);
}

// ---------------------------------------------------------------------------
__global__ void reset_kernel() {
    g_seg[threadIdx.x] = 0;
}

// ---------------------------------------------------------------------------
__device__ __forceinline__ float mufu_tanh(float x) {
    float y; asm("tanh.approx.f32 %0, %1;" : "=f"(y) : "f"(x)); return y;
}

// one LSTM step. s = (0.5*gx0, 0.5*gx1, gx2, 0.5*gx3); ws likewise scaled.
__device__ __forceinline__ void lstm_step(
    const float4 s,
    const float ws0, const float ws1, const float ws2, const float ws3,
    float& h, float& c)
{
    const float u0 = fmaf(ws0, h, s.x);
    const float u1 = fmaf(ws1, h, s.y);
    const float u2 = fmaf(ws2, h, s.z);
    const float u3 = fmaf(ws3, h, s.w);

    const float ig = fmaf(0.5f, mufu_tanh(u0), 0.5f);   // sigmoid
    const float fg = fmaf(0.5f, mufu_tanh(u1), 0.5f);   // sigmoid
    const float gc = mufu_tanh(u2);                     // tanh
    const float og = fmaf(0.5f, mufu_tanh(u3), 0.5f);   // sigmoid

    c = fmaf(fg, c, ig * gc);
    h = og * mufu_tanh(c);
}

// ---------------------------------------------------------------------------
__global__ __launch_bounds__(PTHREADS, 4) void fused_kernel(
    const float* __restrict__ x,
    const float* __restrict__ W_ih,
    const float* __restrict__ b_ih,
    const float* __restrict__ b_hh,
    const float* __restrict__ W_hh,
    const float* __restrict__ h0,
    const float* __restrict__ c0,
    float* __restrict__ out)
{
    if (blockIdx.x < PBLOCKS) {
        // ================= PRODUCER =================
        __shared__ float4 sW[4][DIM / 4];   // 16 KB

        const int tid = threadIdx.x;
        const float4* W4 = reinterpret_cast<const float4*>(W_ih);
        for (int i = tid; i < DIM; i += PTHREADS) {
            sW[i >> 8][i & 255] = W4[i];
        }
        __syncthreads();

        const int warp = tid >> 5;
        const int lane = tid & 31;
        const int row  = blockIdx.x * ROWS_PER_BLOCK + warp;

        const float4* x4 =
            reinterpret_cast<const float4*>(x) + (size_t)row * (DIM / 4);

        // front-batch 8 loads (one row) -> MLP 8, modest reg pressure
        float4 xv[8];
#pragma unroll
        for (int j = 0; j < 8; ++j) xv[j] = __ldg(&x4[j * 32 + lane]);

        float a0 = 0.f, a1 = 0.f, a2 = 0.f, a3 = 0.f;
#pragma unroll
        for (int j = 0; j < 8; ++j) {
            const int idx = j * 32 + lane;
            float4 w;
            w = sW[0][idx];
            a0 = fmaf(xv[j].x, w.x, fmaf(xv[j].y, w.y,
                 fmaf(xv[j].z, w.z, fmaf(xv[j].w, w.w, a0))));
            w = sW[1][idx];
            a1 = fmaf(xv[j].x, w.x, fmaf(xv[j].y, w.y,
                 fmaf(xv[j].z, w.z, fmaf(xv[j].w, w.w, a1))));
            w = sW[2][idx];
            a2 = fmaf(xv[j].x, w.x, fmaf(xv[j].y, w.y,
                 fmaf(xv[j].z, w.z, fmaf(xv[j].w, w.w, a2))));
            w = sW[3][idx];
            a3 = fmaf(xv[j].x, w.x, fmaf(xv[j].y, w.y,
                 fmaf(xv[j].z, w.z, fmaf(xv[j].w, w.w, a3))));
        }
#pragma unroll
        for (int off = 16; off > 0; off >>= 1) {
            a0 += __shfl_xor_sync(0xffffffffu, a0, off);
            a1 += __shfl_xor_sync(0xffffffffu, a1, off);
            a2 += __shfl_xor_sync(0xffffffffu, a2, off);
            a3 += __shfl_xor_sync(0xffffffffu, a3, off);
        }
        if (lane == 0) {
            const float g0 = a0 + b_ih[0] + b_hh[0];
            const float g1 = a1 + b_ih[1] + b_hh[1];
            const float g2 = a2 + b_ih[2] + b_hh[2];
            const float g3 = a3 + b_ih[3] + b_hh[3];
            g_gatesT[gidx(row)] =
                make_float4(0.5f * g0, 0.5f * g1, g2, 0.5f * g3);
        }

        __syncthreads();
        __threadfence();
        if (tid == 0) atomicAdd(&g_seg[blockIdx.x / BLOCKS_PER_SEG], 1);

    } else {
        // ================= CONSUMER =================
        if (threadIdx.x >= 32) return;

        const int w    = blockIdx.x - PBLOCKS;      // scan warp id, 0..127
        const int lane = threadIdx.x;
        const int cid  = w * 32 + lane;             // chunk id
        const int base = cid * CHUNK - BURN;        // burn start (may be <0)

        const float ws0 = 0.5f * W_hh[0];
        const float ws1 = 0.5f * W_hh[1];
        const float ws2 = W_hh[2];
        const float ws3 = 0.5f * W_hh[3];
        const float h0v = __ldg(h0);
        const float c0v = __ldg(c0);

        // wait for the (at most two) 256-row segments covering this window
        const int s0 = (w == 0) ? 0 : (w - 1);
        while (atomicAdd(&g_seg[s0], 0) < BLOCKS_PER_SEG) __nanosleep(64);
        while (atomicAdd(&g_seg[w],  0) < BLOCKS_PER_SEG) __nanosleep(64);
        __threadfence();

        float h = 0.f, c = 0.f;

        float4 buf[4], nbuf[4];
#pragma unroll
        for (int k = 0; k < 4; ++k) {
            int t = base + k;
            t = t < 0 ? 0 : t;
            buf[k] = __ldg(&g_gatesT[gidx(t)]);
        }

        // ---- burn-in: 48 steps, no stores ----
#pragma unroll
        for (int jb = 0; jb < BURN; jb += 4) {
#pragma unroll
            for (int k = 0; k < 4; ++k) {
                int t = base + jb + 4 + k;
                t = t < 0 ? 0 : t;
                nbuf[k] = __ldg(&g_gatesT[gidx(t)]);
            }
#pragma unroll
            for (int k = 0; k < 4; ++k)
                lstm_step(buf[k], ws0, ws1, ws2, ws3, h, c);
#pragma unroll
            for (int k = 0; k < 4; ++k) buf[k] = nbuf[k];
        }

        // chunk 0 starts from the true initial state
        if (cid == 0) { h = h0v; c = c0v; }

        // ---- emit 8 steps ----
        const int t_begin = cid * CHUNK;
#pragma unroll
        for (int k = 0; k < 4; ++k)
            nbuf[k] = __ldg(&g_gatesT[gidx(t_begin + 4 + k)]);
#pragma unroll
        for (int k = 0; k < 4; ++k) {
            lstm_step(buf[k], ws0, ws1, ws2, ws3, h, c);
            out[t_begin + k] = h;
        }
#pragma unroll
        for (int k = 0; k < 4; ++k) {
            lstm_step(nbuf[k], ws0, ws1, ws2, ws3, h, c);
            out[t_begin + 4 + k] = h;
        }
    }
}

// ---------------------------------------------------------------------------
extern "C" void kernel_launch(void* const* d_in, const int* in_sizes, int n_in,
                              void* d_out, int out_size)
{
    const float* x    = (const float*)d_in[0];
    const float* W_ih = (const float*)d_in[1];
    const float* W_hh = (const float*)d_in[2];
    const float* b_ih = (const float*)d_in[3];
    const float* b_hh = (const float*)d_in[4];
    const float* h0   = (const float*)d_in[5];
    const float* c0   = (const float*)d_in[6];
    float* out = (float*)d_out;

    reset_kernel<<<1, NSEG>>>();
    fused_kernel<<<PBLOCKS + CWARPS, PTHREADS>>>(
        x, W_ih, b_ih, b_hh, W_hh, h0, c0, out);
}

// round 8
// speedup vs baseline: 1.4022x; 1.4022x over previous
#include <cuda_runtime.h>
#include <cuda_bf16.h>

// LSTMHead, round 8: back to TWO kernels (fusion empirically net-negative:
// R5 +34us, R6 +5us, R7 +9us vs the R4 split baseline).
//
// Kernel 1 (gates): each warp computes TWO rows with a j-pipelined inner loop:
//   - next-j x float4s prefetched (double buffer, 16 x-regs live),
//   - W float4s loaded from smem ONCE per j and shared across both rows
//     -> 16 LDS.128/row (half of R4), loads continuously in flight.
//   ~60 regs, launch_bounds(256,4) -> 32 warps/SM.
// Kernel 2 (scan): 4096 chunks of 8 steps, 48 burn-in, one chunk per lane,
//   128 single-warp blocks (one per SM). tanh.approx activations with
//   sigmoid(z)=0.5+0.5*tanh(z/2); sigmoid gates pre-scaled by 0.5.

#define SEQ   32768
#define DIM   1024
#define CHUNK 8
#define BURN  48
#define NCHUNK (SEQ / CHUNK)        // 4096
#define CWARPS (NCHUNK / 32)        // 128
#define TROWS  (SEQ / CHUNK)        // 4096

// transposed, pre-scaled gate pre-activations (512 KB, L2-resident)
__device__ float4 g_gatesT[SEQ];

__device__ __forceinline__ int gidx(int t) {
    return (t & (CHUNK - 1)) * TROWS + (t >> 3);
}

// ---------------------------------------------------------------------------
// Kernel 1: gates GEMV, 2 rows/warp, j-pipelined.
// ---------------------------------------------------------------------------
__global__ __launch_bounds__(256, 4) void gates_kernel(
    const float* __restrict__ x,
    const float* __restrict__ W_ih,
    const float* __restrict__ b_ih,
    const float* __restrict__ b_hh)
{
    __shared__ float4 sW[4][DIM / 4];   // 16 KB

    const int tid = threadIdx.x;
    const float4* W4 = reinterpret_cast<const float4*>(W_ih);
    for (int i = tid; i < DIM; i += 256) {
        sW[i >> 8][i & 255] = W4[i];
    }
    __syncthreads();

    const int warp = tid >> 5;
    const int lane = tid & 31;
    const int rowA = (blockIdx.x * 8 + warp) * 2;
    const int rowB = rowA + 1;

    const float4* xA =
        reinterpret_cast<const float4*>(x) + (size_t)rowA * (DIM / 4);
    const float4* xB =
        reinterpret_cast<const float4*>(x) + (size_t)rowB * (DIM / 4);

    // double-buffered per-j x loads: 2 LDG continuously in flight per warp
    float4 xa[2], xb[2];
    xa[0] = __ldg(&xA[lane]);
    xb[0] = __ldg(&xB[lane]);

    float a0 = 0.f, a1 = 0.f, a2 = 0.f, a3 = 0.f;
    float e0 = 0.f, e1 = 0.f, e2 = 0.f, e3 = 0.f;

#pragma unroll
    for (int j = 0; j < 8; ++j) {
        const int cur = j & 1, nxt = cur ^ 1;
        if (j < 7) {
            xa[nxt] = __ldg(&xA[(j + 1) * 32 + lane]);
            xb[nxt] = __ldg(&xB[(j + 1) * 32 + lane]);
        }
        const int idx = j * 32 + lane;
        const float4 w0 = sW[0][idx];
        const float4 w1 = sW[1][idx];
        const float4 w2 = sW[2][idx];
        const float4 w3 = sW[3][idx];
        const float4 va = xa[cur];
        const float4 vb = xb[cur];

        a0 = fmaf(va.x, w0.x, fmaf(va.y, w0.y, fmaf(va.z, w0.z, fmaf(va.w, w0.w, a0))));
        a1 = fmaf(va.x, w1.x, fmaf(va.y, w1.y, fmaf(va.z, w1.z, fmaf(va.w, w1.w, a1))));
        a2 = fmaf(va.x, w2.x, fmaf(va.y, w2.y, fmaf(va.z, w2.z, fmaf(va.w, w2.w, a2))));
        a3 = fmaf(va.x, w3.x, fmaf(va.y, w3.y, fmaf(va.z, w3.z, fmaf(va.w, w3.w, a3))));
        e0 = fmaf(vb.x, w0.x, fmaf(vb.y, w0.y, fmaf(vb.z, w0.z, fmaf(vb.w, w0.w, e0))));
        e1 = fmaf(vb.x, w1.x, fmaf(vb.y, w1.y, fmaf(vb.z, w1.z, fmaf(vb.w, w1.w, e1))));
        e2 = fmaf(vb.x, w2.x, fmaf(vb.y, w2.y, fmaf(vb.z, w2.z, fmaf(vb.w, w2.w, e2))));
        e3 = fmaf(vb.x, w3.x, fmaf(vb.y, w3.y, fmaf(vb.z, w3.z, fmaf(vb.w, w3.w, e3))));
    }

#pragma unroll
    for (int off = 16; off > 0; off >>= 1) {
        a0 += __shfl_xor_sync(0xffffffffu, a0, off);
        a1 += __shfl_xor_sync(0xffffffffu, a1, off);
        a2 += __shfl_xor_sync(0xffffffffu, a2, off);
        a3 += __shfl_xor_sync(0xffffffffu, a3, off);
        e0 += __shfl_xor_sync(0xffffffffu, e0, off);
        e1 += __shfl_xor_sync(0xffffffffu, e1, off);
        e2 += __shfl_xor_sync(0xffffffffu, e2, off);
        e3 += __shfl_xor_sync(0xffffffffu, e3, off);
    }
    if (lane == 0) {
        const float bb0 = b_ih[0] + b_hh[0];
        const float bb1 = b_ih[1] + b_hh[1];
        const float bb2 = b_ih[2] + b_hh[2];
        const float bb3 = b_ih[3] + b_hh[3];
        g_gatesT[gidx(rowA)] = make_float4(
            0.5f * (a0 + bb0), 0.5f * (a1 + bb1),
            (a2 + bb2),        0.5f * (a3 + bb3));
        g_gatesT[gidx(rowB)] = make_float4(
            0.5f * (e0 + bb0), 0.5f * (e1 + bb1),
            (e2 + bb2),        0.5f * (e3 + bb3));
    }
}

// ---------------------------------------------------------------------------
// Kernel 2: SIMD chunk-parallel scan.
// ---------------------------------------------------------------------------
__device__ __forceinline__ float mufu_tanh(float x) {
    float y; asm("tanh.approx.f32 %0, %1;" : "=f"(y) : "f"(x)); return y;
}

// one LSTM step. s = (0.5*gx0, 0.5*gx1, gx2, 0.5*gx3); ws likewise scaled.
__device__ __forceinline__ void lstm_step(
    const float4 s,
    const float ws0, const float ws1, const float ws2, const float ws3,
    float& h, float& c)
{
    const float u0 = fmaf(ws0, h, s.x);
    const float u1 = fmaf(ws1, h, s.y);
    const float u2 = fmaf(ws2, h, s.z);
    const float u3 = fmaf(ws3, h, s.w);

    const float ig = fmaf(0.5f, mufu_tanh(u0), 0.5f);   // sigmoid
    const float fg = fmaf(0.5f, mufu_tanh(u1), 0.5f);   // sigmoid
    const float gc = mufu_tanh(u2);                     // tanh
    const float og = fmaf(0.5f, mufu_tanh(u3), 0.5f);   // sigmoid

    c = fmaf(fg, c, ig * gc);
    h = og * mufu_tanh(c);
}

__global__ __launch_bounds__(32) void scan_kernel(
    const float* __restrict__ W_hh,
    const float* __restrict__ h0,
    const float* __restrict__ c0,
    float* __restrict__ out)
{
    const int lane = threadIdx.x;
    const int cid  = blockIdx.x * 32 + lane;    // chunk id
    const int base = cid * CHUNK - BURN;        // burn start (may be <0)

    const float ws0 = 0.5f * W_hh[0];
    const float ws1 = 0.5f * W_hh[1];
    const float ws2 = W_hh[2];
    const float ws3 = 0.5f * W_hh[3];
    const float h0v = __ldg(h0);
    const float c0v = __ldg(c0);

    float h = 0.f, c = 0.f;

    float4 buf[4], nbuf[4];
#pragma unroll
    for (int k = 0; k < 4; ++k) {
        int t = base + k;
        t = t < 0 ? 0 : t;
        buf[k] = __ldg(&g_gatesT[gidx(t)]);
    }

    // ---- burn-in: 48 steps, no stores ----
#pragma unroll
    for (int jb = 0; jb < BURN; jb += 4) {
#pragma unroll
        for (int k = 0; k < 4; ++k) {
            int t = base + jb + 4 + k;
            t = t < 0 ? 0 : t;
            nbuf[k] = __ldg(&g_gatesT[gidx(t)]);
        }
#pragma unroll
        for (int k = 0; k < 4; ++k)
            lstm_step(buf[k], ws0, ws1, ws2, ws3, h, c);
#pragma unroll
        for (int k = 0; k < 4; ++k) buf[k] = nbuf[k];
    }

    // chunk 0 starts from the true initial state
    if (cid == 0) { h = h0v; c = c0v; }

    // ---- emit 8 steps ----
    const int t_begin = cid * CHUNK;
#pragma unroll
    for (int k = 0; k < 4; ++k)
        nbuf[k] = __ldg(&g_gatesT[gidx(t_begin + 4 + k)]);
#pragma unroll
    for (int k = 0; k < 4; ++k) {
        lstm_step(buf[k], ws0, ws1, ws2, ws3, h, c);
        out[t_begin + k] = h;
    }
#pragma unroll
    for (int k = 0; k < 4; ++k) {
        lstm_step(nbuf[k], ws0, ws1, ws2, ws3, h, c);
        out[t_begin + 4 + k] = h;
    }
}

// ---------------------------------------------------------------------------
extern "C" void kernel_launch(void* const* d_in, const int* in_sizes, int n_in,
                              void* d_out, int out_size)
{
    const float* x    = (const float*)d_in[0];
    const float* W_ih = (const float*)d_in[1];
    const float* W_hh = (const float*)d_in[2];
    const float* b_ih = (const float*)d_in[3];
    const float* b_hh = (const float*)d_in[4];
    const float* h0   = (const float*)d_in[5];
    const float* c0   = (const float*)d_in[6];
    float* out = (float*)d_out;

    gates_kernel<<<SEQ / 16, 256>>>(x, W_ih, b_ih, b_hh);   // 2048 blocks
    scan_kernel<<<CWARPS, 32>>>(W_hh, h0, c0, out);         // 128 warps
}